// round 7
// baseline (speedup 1.0000x reference)
#include <cuda_runtime.h>
#include <cstdint>

#define N_TOK 343
#define BATCH 256
#define HEADS 6
#define HDIM  32
#define CDIM  192
#define ODIM  576            // 3*C
#define MROWS 87808          // BATCH*N_TOK
#define NN2   117649         // 343*343
#define SCALE 0.17677669529663687f
#define NEGBIG (-1e30f)

// ---------------- scratch (device globals: no runtime allocation allowed) ----
// NOTE: only reference these from device code (host shadow trap — R5 bug).
__device__ float g_qkv[(size_t)MROWS * ODIM];   // [B*N, 3C]
__device__ float g_att[(size_t)MROWS * CDIM];   // [B*N, C]
__device__ float g_bias[HEADS * NN2];           // [H, N, N]

// ---------------- common helpers -------------------------------------------
__device__ __forceinline__ float to_tf32(float x) {
    uint32_t u;
    asm("cvt.rna.tf32.f32 %0, %1;" : "=r"(u) : "f"(x));
    return __uint_as_float(u);
}

__device__ __forceinline__ void mma_tf32(float* d, const uint32_t* a, const uint32_t* b) {
    asm volatile(
        "mma.sync.aligned.m16n8k8.row.col.f32.tf32.tf32.f32 "
        "{%0,%1,%2,%3}, {%4,%5,%6,%7}, {%8,%9}, {%0,%1,%2,%3};\n"
        : "+f"(d[0]), "+f"(d[1]), "+f"(d[2]), "+f"(d[3])
        : "r"(a[0]), "r"(a[1]), "r"(a[2]), "r"(a[3]), "r"(b[0]), "r"(b[1]));
}

// ---------------- kernel 1: gather relative-position bias ------------------
__global__ void bias_gather_kernel(const float* __restrict__ tab,
                                   const int* __restrict__ idx) {
    int p = blockIdx.x * 256 + threadIdx.x;
    if (p < NN2) {
        int id = idx[p];
        #pragma unroll
        for (int h = 0; h < HEADS; h++)
            g_bias[h * NN2 + p] = tab[id * HEADS + h];
    }
}

// ================= tensor-core GEMM via mma.sync (tf32) =====================
// (unchanged from R6 — passing baseline)
#define GK  192
#define GBK 96
#define NST 12

#define SM_GEMM_FLOATS (12288 + 6144)      // 73728 bytes

template <int DST>
__global__ __launch_bounds__(256, 2)
void gemm_tc(const float* __restrict__ Ain, const float* __restrict__ W,
             const float* __restrict__ bias, float* __restrict__ outp, int ocols) {
    const float* A   = (DST == 0) ? Ain : (const float*)g_att;
    float*       out = (DST == 0) ? (float*)g_qkv : outp;

    extern __shared__ float sm[];
    float* As = sm;            // 12288 floats
    float* Bs = sm + 12288;    // 6144 floats

    const int t    = threadIdx.x;
    const int lane = t & 31;
    const int wid  = t >> 5;
    const int o0   = blockIdx.x * 64;
    const int m0   = blockIdx.y * 128;
    const int wr   = wid >> 1;
    const int wc   = wid & 1;

    float acc[2][4][4];
    #pragma unroll
    for (int im = 0; im < 2; im++)
        #pragma unroll
        for (int jn = 0; jn < 4; jn++)
            #pragma unroll
            for (int q = 0; q < 4; q++) acc[im][jn][q] = 0.f;

    for (int chunk = 0; chunk < 2; chunk++) {
        const int k0 = chunk * GBK;
        __syncthreads();

        #pragma unroll
        for (int u = 0; u < 12; u++) {
            int e = u * 256 + t;
            int r = e / 24;
            int c = (e % 24) * 4;
            float4 v = *(const float4*)(A + (size_t)(m0 + r) * GK + k0 + c);
            int grp = r & 7, hm = (r >> 3) & 1, mb = r >> 4;
            int s = c >> 3, hk = (c >> 2) & 1;
            int base = (((mb * NST + s) * 32) + grp * 4) * 4 + hm + 2 * hk;
            As[base + 0]  = to_tf32(v.x);
            As[base + 4]  = to_tf32(v.y);
            As[base + 8]  = to_tf32(v.z);
            As[base + 12] = to_tf32(v.w);
        }
        #pragma unroll
        for (int u = 0; u < 6; u++) {
            int e = u * 256 + t;
            int j = e / 24;
            int c = (e % 24) * 4;
            float4 v = *(const float4*)(W + (size_t)(o0 + j) * GK + k0 + c);
            int grp = j & 7, nb = j >> 3;
            int s = c >> 3, hk = (c >> 2) & 1;
            int base = (((nb * NST + s) * 32) + grp * 4) * 2 + hk;
            Bs[base + 0] = to_tf32(v.x);
            Bs[base + 2] = to_tf32(v.y);
            Bs[base + 4] = to_tf32(v.z);
            Bs[base + 6] = to_tf32(v.w);
        }
        __syncthreads();

        #pragma unroll
        for (int s = 0; s < NST; s++) {
            uint32_t a[2][4];
            #pragma unroll
            for (int im = 0; im < 2; im++) {
                const uint4 av = *(const uint4*)&As[(((wr * 2 + im) * NST + s) * 32 + lane) * 4];
                a[im][0] = av.x; a[im][1] = av.y; a[im][2] = av.z; a[im][3] = av.w;
            }
            uint32_t b[4][2];
            #pragma unroll
            for (int jn = 0; jn < 4; jn++) {
                const uint2 bv = *(const uint2*)&Bs[(((wc * 4 + jn) * NST + s) * 32 + lane) * 2];
                b[jn][0] = bv.x; b[jn][1] = bv.y;
            }
            #pragma unroll
            for (int im = 0; im < 2; im++)
                #pragma unroll
                for (int jn = 0; jn < 4; jn++)
                    mma_tf32(acc[im][jn], a[im], b[jn]);
        }
    }

    const int grp = lane >> 2;
    const int tig = lane & 3;
    #pragma unroll
    for (int im = 0; im < 2; im++) {
        #pragma unroll
        for (int jn = 0; jn < 4; jn++) {
            int col = o0 + wc * 32 + jn * 8 + tig * 2;
            float b0 = 0.f, b1 = 0.f;
            if (bias) { b0 = bias[col]; b1 = bias[col + 1]; }
            int row0 = m0 + wr * 32 + im * 16 + grp;
            float2 v0 = make_float2(acc[im][jn][0] + b0, acc[im][jn][1] + b1);
            float2 v1 = make_float2(acc[im][jn][2] + b0, acc[im][jn][3] + b1);
            *(float2*)(out + (size_t)row0 * ocols + col)       = v0;
            *(float2*)(out + (size_t)(row0 + 8) * ocols + col) = v1;
        }
    }
}

// ================= kernel 3: tensor-core flash attention ====================
// Per CTA: one (b, h, 128-query tile). 8 warps, warp tile 16(M)x64(N keys).
// S = QK^T and O = PV via mma.sync m16n8k8 tf32. Softmax state lives in the
// accumulator-row lanes (grp, grp+8): only 2 shfls over tig bits per row.
//
// SMEM (floats):
//   Qf [8 mb][4 ks][32 lanes][4]  = 4096   A-fragments of Q (persistent)
//   Kf [8 nb][4 ks][32 lanes][2]  = 2048   B-fragments of K (per tile)
//   Vf [8 ks2][4 nb][32 lanes][2] = 2048   B-fragments of V (per tile)
//   Pf [8 warps][8 ks2][128]      = 8192   per-warp P relayout buffer
//   Bm [128][68]                  = 8704   bias+mask tile (row-major, padded)
#define ATT_SM_FLOATS (4096 + 2048 + 2048 + 8192 + 8704)   // 25088 -> 100352 B

__global__ __launch_bounds__(256, 2) void attn_mma(const float* __restrict__ mask) {
    extern __shared__ float sm[];
    float* Qf = sm;                    // 4096
    float* Kf = sm + 4096;             // 2048
    float* Vf = sm + 6144;             // 2048
    float* Pf = sm + 8192;             // 8192
    float* Bm = sm + 16384;            // 8704

    const int t    = threadIdx.x;
    const int lane = t & 31;
    const int wid  = t >> 5;
    const int grp  = lane >> 2;
    const int tig  = lane & 3;

    const int q0 = blockIdx.x * 128;
    const int h  = blockIdx.y;
    const int b  = blockIdx.z;
    const int w  = b & 63;

    const float* qptr = g_qkv + (size_t)b * N_TOK * ODIM + h * HDIM;
    const float* kptr = qptr + CDIM;
    const float* vptr = qptr + 2 * CDIM;
    const float* mrow = mask  + (size_t)w * NN2;
    const float* brow = g_bias + (size_t)h * NN2;

    // ---- stage Q [128x32] into A-fragment order (tf32), once ----
    {
        int r  = t >> 1;                 // 0..127
        int qi = q0 + r;
        int mb = r >> 4, g = r & 7, hm = (r >> 3) & 1;
        int db = (t & 1) * 16;
        #pragma unroll
        for (int c4 = 0; c4 < 4; c4++) {
            int d = db + c4 * 4;
            float4 v = make_float4(0.f, 0.f, 0.f, 0.f);
            if (qi < N_TOK) v = *(const float4*)(qptr + (size_t)qi * ODIM + d);
            int ks = d >> 3, hk = (d >> 2) & 1;
            float* dst = &Qf[mb * 512 + ks * 128 + g * 16 + hm + 2 * hk];
            dst[0]  = to_tf32(v.x);
            dst[4]  = to_tf32(v.y);
            dst[8]  = to_tf32(v.z);
            dst[12] = to_tf32(v.w);
        }
    }

    float mr[2], lr[2];
    mr[0] = NEGBIG; mr[1] = NEGBIG; lr[0] = 0.f; lr[1] = 0.f;
    float o[4][4];
    #pragma unroll
    for (int nb = 0; nb < 4; nb++)
        #pragma unroll
        for (int q = 0; q < 4; q++) o[nb][q] = 0.f;

    for (int kt = 0; kt < 6; kt++) {
        const int k0 = kt * 64;
        __syncthreads();   // prior tile's S/PV done reading Kf/Vf/Bm (+Q stage)

        // ---- stage K,V [64x32] into B-fragment order (tf32) ----
        {
            int j  = t >> 2;
            int kj = k0 + j;
            bool vld = kj < N_TOK;
            int db = (t & 3) * 8;
            float4 k0v = make_float4(0.f, 0.f, 0.f, 0.f), k1v = k0v;
            float4 v0v = k0v, v1v = k0v;
            if (vld) {
                k0v = *(const float4*)(kptr + (size_t)kj * ODIM + db);
                k1v = *(const float4*)(kptr + (size_t)kj * ODIM + db + 4);
                v0v = *(const float4*)(vptr + (size_t)kj * ODIM + db);
                v1v = *(const float4*)(vptr + (size_t)kj * ODIM + db + 4);
            }
            {   // K: element (key j, d) -> Kf[(j>>3)*256 + (d>>3)*64 + (j&7)*8 + (d&3)*2 + ((d>>2)&1)]
                float* kd = &Kf[(j >> 3) * 256 + (db >> 3) * 64 + (j & 7) * 8];
                float4 w0 = make_float4(to_tf32(k0v.x), to_tf32(k1v.x),
                                        to_tf32(k0v.y), to_tf32(k1v.y));
                float4 w1 = make_float4(to_tf32(k0v.z), to_tf32(k1v.z),
                                        to_tf32(k0v.w), to_tf32(k1v.w));
                *(float4*)(kd + 0) = w0;
                *(float4*)(kd + 4) = w1;
            }
            {   // V: element (k=j, n=d) -> Vf[(j>>3)*256 + (d>>3)*64 + (d&7)*8 + ((j&7)&3)*2 + ((j&7)>>2)]
                float* vd = &Vf[(j >> 3) * 256 + (db >> 3) * 64 + ((j & 7) & 3) * 2 + ((j & 7) >> 2)];
                vd[0]  = to_tf32(v0v.x);
                vd[8]  = to_tf32(v0v.y);
                vd[16] = to_tf32(v0v.z);
                vd[24] = to_tf32(v0v.w);
                vd[32] = to_tf32(v1v.x);
                vd[40] = to_tf32(v1v.y);
                vd[48] = to_tf32(v1v.z);
                vd[56] = to_tf32(v1v.w);
            }
        }

        // ---- stage bias+mask tile [128x64] (coalesced, summed) ----
        #pragma unroll
        for (int u = 0; u < 32; u++) {
            int e  = u * 256 + t;
            int r  = e >> 6;
            int c  = e & 63;
            int qi = q0 + r;
            int kj = k0 + c;
            float bm;
            if (qi >= N_TOK)      bm = 0.f;
            else if (kj >= N_TOK) bm = NEGBIG;
            else                  bm = brow[qi * N_TOK + kj] + mrow[qi * N_TOK + kj];
            Bm[r * 68 + c] = bm;
        }
        __syncthreads();

        // ---- S = Q K^T : warp tile 16x64 ----
        float s[8][4];
        #pragma unroll
        for (int nb = 0; nb < 8; nb++)
            #pragma unroll
            for (int q = 0; q < 4; q++) s[nb][q] = 0.f;

        #pragma unroll
        for (int ks = 0; ks < 4; ks++) {
            uint32_t a[4];
            const uint4 av = *(const uint4*)&Qf[wid * 512 + ks * 128 + lane * 4];
            a[0] = av.x; a[1] = av.y; a[2] = av.z; a[3] = av.w;
            #pragma unroll
            for (int nb = 0; nb < 8; nb++) {
                uint32_t bfr[2];
                const uint2 bv = *(const uint2*)&Kf[nb * 256 + ks * 64 + lane * 2];
                bfr[0] = bv.x; bfr[1] = bv.y;
                mma_tf32(s[nb], a, bfr);
            }
        }

        // ---- online softmax (rows grp, grp+8 of warp tile) ----
        const int r0 = wid * 16 + grp;   // local row 0..127
        float rmax0 = NEGBIG, rmax1 = NEGBIG;
        #pragma unroll
        for (int nb = 0; nb < 8; nb++) {
            float2 bm0 = *(const float2*)&Bm[r0 * 68 + nb * 8 + 2 * tig];
            float2 bm1 = *(const float2*)&Bm[(r0 + 8) * 68 + nb * 8 + 2 * tig];
            s[nb][0] = s[nb][0] * SCALE + bm0.x;
            s[nb][1] = s[nb][1] * SCALE + bm0.y;
            s[nb][2] = s[nb][2] * SCALE + bm1.x;
            s[nb][3] = s[nb][3] * SCALE + bm1.y;
            rmax0 = fmaxf(rmax0, fmaxf(s[nb][0], s[nb][1]));
            rmax1 = fmaxf(rmax1, fmaxf(s[nb][2], s[nb][3]));
        }
        rmax0 = fmaxf(rmax0, __shfl_xor_sync(0xffffffffu, rmax0, 1));
        rmax0 = fmaxf(rmax0, __shfl_xor_sync(0xffffffffu, rmax0, 2));
        rmax1 = fmaxf(rmax1, __shfl_xor_sync(0xffffffffu, rmax1, 1));
        rmax1 = fmaxf(rmax1, __shfl_xor_sync(0xffffffffu, rmax1, 2));

        float mn0 = fmaxf(mr[0], rmax0);
        float mn1 = fmaxf(mr[1], rmax1);
        float al0 = __expf(mr[0] - mn0);
        float al1 = __expf(mr[1] - mn1);
        mr[0] = mn0; mr[1] = mn1;

        float rs0 = 0.f, rs1 = 0.f;
        float* pw = Pf + wid * 1024 + grp * 16;
        const int off0 = ((2 * tig) & 3) * 4 + ((2 * tig) >> 2) * 2;
        const int off1 = ((2 * tig + 1) & 3) * 4 + ((2 * tig + 1) >> 2) * 2;
        #pragma unroll
        for (int nb = 0; nb < 8; nb++) {
            float p00 = __expf(s[nb][0] - mn0);
            float p01 = __expf(s[nb][1] - mn0);
            float p10 = __expf(s[nb][2] - mn1);
            float p11 = __expf(s[nb][3] - mn1);
            rs0 += p00 + p01;
            rs1 += p10 + p11;
            // S col-block nb == PV k-block; write P in PV A-fragment layout
            *(float2*)&pw[nb * 128 + off0] = make_float2(to_tf32(p00), to_tf32(p10));
            *(float2*)&pw[nb * 128 + off1] = make_float2(to_tf32(p01), to_tf32(p11));
        }
        rs0 += __shfl_xor_sync(0xffffffffu, rs0, 1);
        rs0 += __shfl_xor_sync(0xffffffffu, rs0, 2);
        rs1 += __shfl_xor_sync(0xffffffffu, rs1, 1);
        rs1 += __shfl_xor_sync(0xffffffffu, rs1, 2);
        lr[0] = lr[0] * al0 + rs0;
        lr[1] = lr[1] * al1 + rs1;

        // rescale O
        #pragma unroll
        for (int nb = 0; nb < 4; nb++) {
            o[nb][0] *= al0; o[nb][1] *= al0;
            o[nb][2] *= al1; o[nb][3] *= al1;
        }
        __syncwarp();   // Pf is per-warp: order STS before cross-lane LDS

        // ---- O += P V : K-dim = 64 keys (8 k-steps) ----
        #pragma unroll
        for (int ks2 = 0; ks2 < 8; ks2++) {
            uint32_t a[4];
            const uint4 av = *(const uint4*)&Pf[wid * 1024 + ks2 * 128 + lane * 4];
            a[0] = av.x; a[1] = av.y; a[2] = av.z; a[3] = av.w;
            #pragma unroll
            for (int nb = 0; nb < 4; nb++) {
                uint32_t bfr[2];
                const uint2 bv = *(const uint2*)&Vf[ks2 * 256 + nb * 64 + lane * 2];
                bfr[0] = bv.x; bfr[1] = bv.y;
                mma_tf32(o[nb], a, bfr);
            }
        }
    }

    // ---- normalize + store [b, n, h*32+d] ----
    {
        float inv0 = 1.f / lr[0];
        float inv1 = 1.f / lr[1];
        int row0 = q0 + wid * 16 + grp;
        int row1 = row0 + 8;
        #pragma unroll
        for (int nb = 0; nb < 4; nb++) {
            int col = h * HDIM + nb * 8 + 2 * tig;
            if (row0 < N_TOK)
                *(float2*)&g_att[((size_t)b * N_TOK + row0) * CDIM + col] =
                    make_float2(o[nb][0] * inv0, o[nb][1] * inv0);
            if (row1 < N_TOK)
                *(float2*)&g_att[((size_t)b * N_TOK + row1) * CDIM + col] =
                    make_float2(o[nb][2] * inv1, o[nb][3] * inv1);
        }
    }
}

// ---------------- launch ----------------------------------------------------
extern "C" void kernel_launch(void* const* d_in, const int* in_sizes, int n_in,
                              void* d_out, int out_size) {
    (void)in_sizes; (void)n_in; (void)out_size;
    const float* x        = (const float*)d_in[0];
    const float* mask     = (const float*)d_in[1];
    const float* qkv_w    = (const float*)d_in[2];
    const float* proj_w   = (const float*)d_in[3];
    const float* proj_b   = (const float*)d_in[4];
    const float* bias_tab = (const float*)d_in[5];
    const int*   rel_idx  = (const int*)d_in[6];
    float* out = (float*)d_out;

    cudaFuncSetAttribute(attn_mma,
                         cudaFuncAttributeMaxDynamicSharedMemorySize,
                         ATT_SM_FLOATS * 4);
    cudaFuncSetAttribute(gemm_tc<0>,
                         cudaFuncAttributeMaxDynamicSharedMemorySize,
                         SM_GEMM_FLOATS * 4);
    cudaFuncSetAttribute(gemm_tc<1>,
                         cudaFuncAttributeMaxDynamicSharedMemorySize,
                         SM_GEMM_FLOATS * 4);

    bias_gather_kernel<<<(NN2 + 255) / 256, 256>>>(bias_tab, rel_idx);
    gemm_tc<0><<<dim3(ODIM / 64, MROWS / 128), 256, SM_GEMM_FLOATS * 4>>>(
        x, qkv_w, nullptr, nullptr, ODIM);
    attn_mma<<<dim3(3, HEADS, BATCH), 256, ATT_SM_FLOATS * 4>>>(mask);
    gemm_tc<1><<<dim3(CDIM / 64, MROWS / 128), 256, SM_GEMM_FLOATS * 4>>>(
        nullptr, proj_w, proj_b, out, CDIM);
}

// round 10
// speedup vs baseline: 1.5914x; 1.5914x over previous
#include <cuda_runtime.h>
#include <cstdint>

#define N_TOK 343
#define BATCH 256
#define HEADS 6
#define HDIM  32
#define CDIM  192
#define ODIM  576            // 3*C
#define MROWS 87808          // BATCH*N_TOK
#define NN2   117649         // 343*343
#define SCALE 0.17677669529663687f
#define LOG2E 1.4426950408889634f
#define QSCALE (SCALE * LOG2E)
#define NEGBIG (-1e30f)

// ---------------- scratch (device globals: no runtime allocation allowed) ----
// NOTE: only reference these from device code (host shadow trap — R5 bug).
__device__ float g_qkv[(size_t)MROWS * ODIM];      // [B*N, 3C]
__device__ float g_att[(size_t)MROWS * CDIM];      // [B*N, C]
__device__ float g_bm[(size_t)64 * HEADS * NN2];   // [NW, H, N, N] (bias+mask)*log2e

// ---------------- common helpers -------------------------------------------
__device__ __forceinline__ float to_tf32(float x) {
    uint32_t u;
    asm("cvt.rna.tf32.f32 %0, %1;" : "=r"(u) : "f"(x));
    return __uint_as_float(u);
}

__device__ __forceinline__ void mma_tf32(float* d, const uint32_t* a, const uint32_t* b) {
    asm volatile(
        "mma.sync.aligned.m16n8k8.row.col.f32.tf32.tf32.f32 "
        "{%0,%1,%2,%3}, {%4,%5,%6,%7}, {%8,%9}, {%0,%1,%2,%3};\n"
        : "+f"(d[0]), "+f"(d[1]), "+f"(d[2]), "+f"(d[3])
        : "r"(a[0]), "r"(a[1]), "r"(a[2]), "r"(a[3]), "r"(b[0]), "r"(b[1]));
}

// ---------------- kernel 1: combined (bias+mask)*log2e precompute ----------
__global__ void bm_precompute(const float* __restrict__ tab,
                              const int* __restrict__ idx,
                              const float* __restrict__ mask) {
    int p = blockIdx.x * 256 + threadIdx.x;
    int w = blockIdx.y;
    if (p < NN2) {
        int id = idx[p];
        float mk = mask[(size_t)w * NN2 + p];
        #pragma unroll
        for (int h = 0; h < HEADS; h++)
            g_bm[((size_t)w * HEADS + h) * NN2 + p] =
                (tab[id * HEADS + h] + mk) * LOG2E;
    }
}

// ================= tensor-core GEMM via mma.sync (tf32) =====================
// (unchanged from R6 — passing baseline)
#define GK  192
#define GBK 96
#define NST 12

#define SM_GEMM_FLOATS (12288 + 6144)      // 73728 bytes

template <int DST>
__global__ __launch_bounds__(256, 2)
void gemm_tc(const float* __restrict__ Ain, const float* __restrict__ W,
             const float* __restrict__ bias, float* __restrict__ outp, int ocols) {
    const float* A   = (DST == 0) ? Ain : (const float*)g_att;
    float*       out = (DST == 0) ? (float*)g_qkv : outp;

    extern __shared__ float sm[];
    float* As = sm;            // 12288 floats
    float* Bs = sm + 12288;    // 6144 floats

    const int t    = threadIdx.x;
    const int lane = t & 31;
    const int wid  = t >> 5;
    const int o0   = blockIdx.x * 64;
    const int m0   = blockIdx.y * 128;
    const int wr   = wid >> 1;
    const int wc   = wid & 1;

    float acc[2][4][4];
    #pragma unroll
    for (int im = 0; im < 2; im++)
        #pragma unroll
        for (int jn = 0; jn < 4; jn++)
            #pragma unroll
            for (int q = 0; q < 4; q++) acc[im][jn][q] = 0.f;

    for (int chunk = 0; chunk < 2; chunk++) {
        const int k0 = chunk * GBK;
        __syncthreads();

        #pragma unroll
        for (int u = 0; u < 12; u++) {
            int e = u * 256 + t;
            int r = e / 24;
            int c = (e % 24) * 4;
            float4 v = *(const float4*)(A + (size_t)(m0 + r) * GK + k0 + c);
            int grp = r & 7, hm = (r >> 3) & 1, mb = r >> 4;
            int s = c >> 3, hk = (c >> 2) & 1;
            int base = (((mb * NST + s) * 32) + grp * 4) * 4 + hm + 2 * hk;
            As[base + 0]  = to_tf32(v.x);
            As[base + 4]  = to_tf32(v.y);
            As[base + 8]  = to_tf32(v.z);
            As[base + 12] = to_tf32(v.w);
        }
        #pragma unroll
        for (int u = 0; u < 6; u++) {
            int e = u * 256 + t;
            int j = e / 24;
            int c = (e % 24) * 4;
            float4 v = *(const float4*)(W + (size_t)(o0 + j) * GK + k0 + c);
            int grp = j & 7, nb = j >> 3;
            int s = c >> 3, hk = (c >> 2) & 1;
            int base = (((nb * NST + s) * 32) + grp * 4) * 2 + hk;
            Bs[base + 0] = to_tf32(v.x);
            Bs[base + 2] = to_tf32(v.y);
            Bs[base + 4] = to_tf32(v.z);
            Bs[base + 6] = to_tf32(v.w);
        }
        __syncthreads();

        #pragma unroll
        for (int s = 0; s < NST; s++) {
            uint32_t a[2][4];
            #pragma unroll
            for (int im = 0; im < 2; im++) {
                const uint4 av = *(const uint4*)&As[(((wr * 2 + im) * NST + s) * 32 + lane) * 4];
                a[im][0] = av.x; a[im][1] = av.y; a[im][2] = av.z; a[im][3] = av.w;
            }
            uint32_t b[4][2];
            #pragma unroll
            for (int jn = 0; jn < 4; jn++) {
                const uint2 bv = *(const uint2*)&Bs[(((wc * 4 + jn) * NST + s) * 32 + lane) * 2];
                b[jn][0] = bv.x; b[jn][1] = bv.y;
            }
            #pragma unroll
            for (int im = 0; im < 2; im++)
                #pragma unroll
                for (int jn = 0; jn < 4; jn++)
                    mma_tf32(acc[im][jn], a[im], b[jn]);
        }
    }

    const int grp = lane >> 2;
    const int tig = lane & 3;
    #pragma unroll
    for (int im = 0; im < 2; im++) {
        #pragma unroll
        for (int jn = 0; jn < 4; jn++) {
            int col = o0 + wc * 32 + jn * 8 + tig * 2;
            float b0 = 0.f, b1 = 0.f;
            if (bias) { b0 = bias[col]; b1 = bias[col + 1]; }
            int row0 = m0 + wr * 32 + im * 16 + grp;
            float2 v0 = make_float2(acc[im][jn][0] + b0, acc[im][jn][1] + b1);
            float2 v1 = make_float2(acc[im][jn][2] + b0, acc[im][jn][3] + b1);
            *(float2*)(out + (size_t)row0 * ocols + col)       = v0;
            *(float2*)(out + (size_t)(row0 + 8) * ocols + col) = v1;
        }
    }
}

// ================= kernel 3: tensor-core flash attention ====================
// Per CTA: one (b, h, 128-query tile). 8 warps, warp tile 16(M)x64(N keys).
// S = QK^T and O = PV via mma.sync m16n8k8 tf32. Q pre-scaled by SCALE*log2e;
// softmax in exp2 domain; bias+mask precombined in g_bm (single gmem stream).
//
// SMEM (floats):
//   Qf [8 mb][4 ks][32 lanes][4]  = 4096   A-fragments of Q (persistent)
//   Kf [8 nb][4 ks][32 lanes][2]  = 2048   B-fragments of K (per tile)
//   Vf [8 ks2][4 nb][32 lanes][2] = 2048   B-fragments of V (per tile)
//   Pf [8 warps][8 ks2][128]      = 8192   per-warp P relayout buffer
//   Bm [128][68]                  = 8704   bias+mask tile (row-major, padded)
#define ATT_SM_FLOATS (4096 + 2048 + 2048 + 8192 + 8704)   // 25088 -> 100352 B

__global__ __launch_bounds__(256, 2) void attn_mma() {
    extern __shared__ float sm[];
    float* Qf = sm;                    // 4096
    float* Kf = sm + 4096;             // 2048
    float* Vf = sm + 6144;             // 2048
    float* Pf = sm + 8192;             // 8192
    float* Bm = sm + 16384;            // 8704

    const int t    = threadIdx.x;
    const int lane = t & 31;
    const int wid  = t >> 5;
    const int grp  = lane >> 2;
    const int tig  = lane & 3;

    const int q0 = blockIdx.x * 128;
    const int h  = blockIdx.y;
    const int b  = blockIdx.z;
    const int w  = b & 63;

    const float* qptr  = g_qkv + (size_t)b * N_TOK * ODIM + h * HDIM;
    const float* kptr  = qptr + CDIM;
    const float* vptr  = qptr + 2 * CDIM;
    const float* bmrow = g_bm + ((size_t)w * HEADS + h) * NN2;

    // ---- stage Q [128x32] into A-fragment order (tf32, pre-scaled), once ----
    {
        int r  = t >> 1;                 // 0..127
        int qi = q0 + r;
        int mb = r >> 4, g = r & 7, hm = (r >> 3) & 1;
        int db = (t & 1) * 16;
        #pragma unroll
        for (int c4 = 0; c4 < 4; c4++) {
            int d = db + c4 * 4;
            float4 v = make_float4(0.f, 0.f, 0.f, 0.f);
            if (qi < N_TOK) v = *(const float4*)(qptr + (size_t)qi * ODIM + d);
            int ks = d >> 3, hk = (d >> 2) & 1;
            float* dst = &Qf[mb * 512 + ks * 128 + g * 16 + hm + 2 * hk];
            dst[0]  = to_tf32(v.x * QSCALE);
            dst[4]  = to_tf32(v.y * QSCALE);
            dst[8]  = to_tf32(v.z * QSCALE);
            dst[12] = to_tf32(v.w * QSCALE);
        }
    }

    float mr[2], lr[2];
    mr[0] = NEGBIG; mr[1] = NEGBIG; lr[0] = 0.f; lr[1] = 0.f;
    float o[4][4];
    #pragma unroll
    for (int nb = 0; nb < 4; nb++)
        #pragma unroll
        for (int q = 0; q < 4; q++) o[nb][q] = 0.f;

    for (int kt = 0; kt < 6; kt++) {
        const int k0 = kt * 64;
        __syncthreads();   // prior tile's S/PV done reading Kf/Vf/Bm (+Q stage)

        // ---- stage bias+mask tile [128x64] (single stream, unroll 8) ----
        #pragma unroll 8
        for (int u = 0; u < 32; u++) {
            int e  = u * 256 + t;
            int r  = e >> 6;
            int c  = e & 63;
            int qi = q0 + r;
            int kj = k0 + c;
            float bm;
            if (qi >= N_TOK)      bm = 0.f;
            else if (kj >= N_TOK) bm = NEGBIG;
            else                  bm = bmrow[qi * N_TOK + kj];
            Bm[r * 68 + c] = bm;
        }

        // ---- stage K,V [64x32] into B-fragment order (tf32) ----
        {
            int j  = t >> 2;
            int kj = k0 + j;
            bool vld = kj < N_TOK;
            int db = (t & 3) * 8;
            float4 k0v = make_float4(0.f, 0.f, 0.f, 0.f), k1v = k0v;
            float4 v0v = k0v, v1v = k0v;
            if (vld) {
                k0v = *(const float4*)(kptr + (size_t)kj * ODIM + db);
                k1v = *(const float4*)(kptr + (size_t)kj * ODIM + db + 4);
                v0v = *(const float4*)(vptr + (size_t)kj * ODIM + db);
                v1v = *(const float4*)(vptr + (size_t)kj * ODIM + db + 4);
            }
            {   // K: (key j, d) -> Kf[(j>>3)*256 + (d>>3)*64 + (j&7)*8 + (d&3)*2 + ((d>>2)&1)]
                float* kd = &Kf[(j >> 3) * 256 + (db >> 3) * 64 + (j & 7) * 8];
                float4 w0 = make_float4(to_tf32(k0v.x), to_tf32(k1v.x),
                                        to_tf32(k0v.y), to_tf32(k1v.y));
                float4 w1 = make_float4(to_tf32(k0v.z), to_tf32(k1v.z),
                                        to_tf32(k0v.w), to_tf32(k1v.w));
                *(float4*)(kd + 0) = w0;
                *(float4*)(kd + 4) = w1;
            }
            {   // V: (k=j, n=d) -> Vf[(j>>3)*256 + (d>>3)*64 + (d&7)*8 + ((j&7)&3)*2 + ((j&7)>>2)]
                float* vd = &Vf[(j >> 3) * 256 + (db >> 3) * 64 + ((j & 7) & 3) * 2 + ((j & 7) >> 2)];
                vd[0]  = to_tf32(v0v.x);
                vd[8]  = to_tf32(v0v.y);
                vd[16] = to_tf32(v0v.z);
                vd[24] = to_tf32(v0v.w);
                vd[32] = to_tf32(v1v.x);
                vd[40] = to_tf32(v1v.y);
                vd[48] = to_tf32(v1v.z);
                vd[56] = to_tf32(v1v.w);
            }
        }
        __syncthreads();

        // ---- S = Q K^T : warp tile 16x64 ----
        float s[8][4];
        #pragma unroll
        for (int nb = 0; nb < 8; nb++)
            #pragma unroll
            for (int q = 0; q < 4; q++) s[nb][q] = 0.f;

        #pragma unroll
        for (int ks = 0; ks < 4; ks++) {
            uint32_t a[4];
            const uint4 av = *(const uint4*)&Qf[wid * 512 + ks * 128 + lane * 4];
            a[0] = av.x; a[1] = av.y; a[2] = av.z; a[3] = av.w;
            #pragma unroll
            for (int nb = 0; nb < 8; nb++) {
                uint32_t bfr[2];
                const uint2 bv = *(const uint2*)&Kf[nb * 256 + ks * 64 + lane * 2];
                bfr[0] = bv.x; bfr[1] = bv.y;
                mma_tf32(s[nb], a, bfr);
            }
        }

        // ---- online softmax in exp2 domain (rows grp, grp+8) ----
        const int r0 = wid * 16 + grp;
        float rmax0 = NEGBIG, rmax1 = NEGBIG;
        #pragma unroll
        for (int nb = 0; nb < 8; nb++) {
            float2 bm0 = *(const float2*)&Bm[r0 * 68 + nb * 8 + 2 * tig];
            float2 bm1 = *(const float2*)&Bm[(r0 + 8) * 68 + nb * 8 + 2 * tig];
            s[nb][0] += bm0.x;
            s[nb][1] += bm0.y;
            s[nb][2] += bm1.x;
            s[nb][3] += bm1.y;
            rmax0 = fmaxf(rmax0, fmaxf(s[nb][0], s[nb][1]));
            rmax1 = fmaxf(rmax1, fmaxf(s[nb][2], s[nb][3]));
        }
        rmax0 = fmaxf(rmax0, __shfl_xor_sync(0xffffffffu, rmax0, 1));
        rmax0 = fmaxf(rmax0, __shfl_xor_sync(0xffffffffu, rmax0, 2));
        rmax1 = fmaxf(rmax1, __shfl_xor_sync(0xffffffffu, rmax1, 1));
        rmax1 = fmaxf(rmax1, __shfl_xor_sync(0xffffffffu, rmax1, 2));

        float mn0 = fmaxf(mr[0], rmax0);
        float mn1 = fmaxf(mr[1], rmax1);
        float al0 = exp2f(mr[0] - mn0);
        float al1 = exp2f(mr[1] - mn1);
        mr[0] = mn0; mr[1] = mn1;

        float rs0 = 0.f, rs1 = 0.f;
        float* pw = Pf + wid * 1024 + grp * 16;
        const int off0 = ((2 * tig) & 3) * 4 + ((2 * tig) >> 2) * 2;
        const int off1 = ((2 * tig + 1) & 3) * 4 + ((2 * tig + 1) >> 2) * 2;
        #pragma unroll
        for (int nb = 0; nb < 8; nb++) {
            float p00 = exp2f(s[nb][0] - mn0);
            float p01 = exp2f(s[nb][1] - mn0);
            float p10 = exp2f(s[nb][2] - mn1);
            float p11 = exp2f(s[nb][3] - mn1);
            rs0 += p00 + p01;
            rs1 += p10 + p11;
            // S col-block nb == PV k-block; write P in PV A-fragment layout
            *(float2*)&pw[nb * 128 + off0] = make_float2(to_tf32(p00), to_tf32(p10));
            *(float2*)&pw[nb * 128 + off1] = make_float2(to_tf32(p01), to_tf32(p11));
        }
        rs0 += __shfl_xor_sync(0xffffffffu, rs0, 1);
        rs0 += __shfl_xor_sync(0xffffffffu, rs0, 2);
        rs1 += __shfl_xor_sync(0xffffffffu, rs1, 1);
        rs1 += __shfl_xor_sync(0xffffffffu, rs1, 2);
        lr[0] = lr[0] * al0 + rs0;
        lr[1] = lr[1] * al1 + rs1;

        // rescale O
        #pragma unroll
        for (int nb = 0; nb < 4; nb++) {
            o[nb][0] *= al0; o[nb][1] *= al0;
            o[nb][2] *= al1; o[nb][3] *= al1;
        }
        __syncwarp();   // Pf is per-warp: order STS before cross-lane LDS

        // ---- O += P V : 64 keys = 8 k-steps ----
        #pragma unroll
        for (int ks2 = 0; ks2 < 8; ks2++) {
            uint32_t a[4];
            const uint4 av = *(const uint4*)&Pf[wid * 1024 + ks2 * 128 + lane * 4];
            a[0] = av.x; a[1] = av.y; a[2] = av.z; a[3] = av.w;
            #pragma unroll
            for (int nb = 0; nb < 4; nb++) {
                uint32_t bfr[2];
                const uint2 bv = *(const uint2*)&Vf[ks2 * 256 + nb * 64 + lane * 2];
                bfr[0] = bv.x; bfr[1] = bv.y;
                mma_tf32(o[nb], a, bfr);
            }
        }
    }

    // ---- normalize + store [b, n, h*32+d] ----
    {
        float inv0 = 1.f / lr[0];
        float inv1 = 1.f / lr[1];
        int row0 = q0 + wid * 16 + grp;
        int row1 = row0 + 8;
        #pragma unroll
        for (int nb = 0; nb < 4; nb++) {
            int col = h * HDIM + nb * 8 + 2 * tig;
            if (row0 < N_TOK)
                *(float2*)&g_att[((size_t)b * N_TOK + row0) * CDIM + col] =
                    make_float2(o[nb][0] * inv0, o[nb][1] * inv0);
            if (row1 < N_TOK)
                *(float2*)&g_att[((size_t)b * N_TOK + row1) * CDIM + col] =
                    make_float2(o[nb][2] * inv1, o[nb][3] * inv1);
        }
    }
}

// ---------------- launch ----------------------------------------------------
extern "C" void kernel_launch(void* const* d_in, const int* in_sizes, int n_in,
                              void* d_out, int out_size) {
    (void)in_sizes; (void)n_in; (void)out_size;
    const float* x        = (const float*)d_in[0];
    const float* mask     = (const float*)d_in[1];
    const float* qkv_w    = (const float*)d_in[2];
    const float* proj_w   = (const float*)d_in[3];
    const float* proj_b   = (const float*)d_in[4];
    const float* bias_tab = (const float*)d_in[5];
    const int*   rel_idx  = (const int*)d_in[6];
    float* out = (float*)d_out;

    cudaFuncSetAttribute(attn_mma,
                         cudaFuncAttributeMaxDynamicSharedMemorySize,
                         ATT_SM_FLOATS * 4);
    cudaFuncSetAttribute(gemm_tc<0>,
                         cudaFuncAttributeMaxDynamicSharedMemorySize,
                         SM_GEMM_FLOATS * 4);
    cudaFuncSetAttribute(gemm_tc<1>,
                         cudaFuncAttributeMaxDynamicSharedMemorySize,
                         SM_GEMM_FLOATS * 4);

    bm_precompute<<<dim3((NN2 + 255) / 256, 64), 256>>>(bias_tab, rel_idx, mask);
    gemm_tc<0><<<dim3(ODIM / 64, MROWS / 128), 256, SM_GEMM_FLOATS * 4>>>(
        x, qkv_w, nullptr, nullptr, ODIM);
    attn_mma<<<dim3(3, HEADS, BATCH), 256, ATT_SM_FLOATS * 4>>>();
    gemm_tc<1><<<dim3(CDIM / 64, MROWS / 128), 256, SM_GEMM_FLOATS * 4>>>(
        nullptr, proj_w, proj_b, out, CDIM);
}

// round 11
// speedup vs baseline: 2.0260x; 1.2731x over previous
#include <cuda_runtime.h>
#include <cstdint>

#define N_TOK 343
#define BATCH 256
#define HEADS 6
#define HDIM  32
#define CDIM  192
#define ODIM  576            // 3*C
#define MROWS 87808          // BATCH*N_TOK
#define NN2   117649         // 343*343
#define SCALE 0.17677669529663687f
#define LOG2E 1.4426950408889634f
#define QSCALE (SCALE * LOG2E)
#define NEGBIG (-1e30f)

// ---------------- scratch (device globals: no runtime allocation allowed) ----
// NOTE: only reference these from device code (host shadow trap — R5 bug).
__device__ float g_qkv[(size_t)MROWS * ODIM];      // [B*N, 3C]
__device__ float g_att[(size_t)MROWS * CDIM];      // [B*N, C]
// bias+mask in MMA-fragment tile order:
// [w][h][qt(3)*6+kt][wid(8)][nb(8)][lane(32)][4]  (8192 floats per 128x64 tile)
__device__ float g_bmt[(size_t)64 * HEADS * 18 * 8192];

// ---------------- common helpers -------------------------------------------
__device__ __forceinline__ float to_tf32(float x) {
    uint32_t u;
    asm("cvt.rna.tf32.f32 %0, %1;" : "=r"(u) : "f"(x));
    return __uint_as_float(u);
}

__device__ __forceinline__ void mma_tf32(float* d, const uint32_t* a, const uint32_t* b) {
    asm volatile(
        "mma.sync.aligned.m16n8k8.row.col.f32.tf32.tf32.f32 "
        "{%0,%1,%2,%3}, {%4,%5,%6,%7}, {%8,%9}, {%0,%1,%2,%3};\n"
        : "+f"(d[0]), "+f"(d[1]), "+f"(d[2]), "+f"(d[3])
        : "r"(a[0]), "r"(a[1]), "r"(a[2]), "r"(a[3]), "r"(b[0]), "r"(b[1]));
}

// ---------------- kernel 1: bias+mask -> fragment-tiled layout -------------
// One CTA per (tile, h, w). Thread (wid, grp, tig) computes the exact 32
// values its attn counterpart consumes, written as 8 coalesced float4s.
__global__ __launch_bounds__(256) void bm_precompute(
        const float* __restrict__ tab,
        const int* __restrict__ idx,
        const float* __restrict__ mask) {
    const int tile = blockIdx.x;        // qt*6 + kt
    const int h    = blockIdx.y;
    const int w    = blockIdx.z;
    const int qt   = tile / 6;
    const int kt   = tile % 6;
    const int t    = threadIdx.x;
    const int lane = t & 31;
    const int wid  = t >> 5;
    const int grp  = lane >> 2;
    const int tig  = lane & 3;

    const int qi0 = qt * 128 + wid * 16 + grp;
    const int qi1 = qi0 + 8;
    const float* mrow = mask + (size_t)w * NN2;

    float* dst = g_bmt + ((((size_t)w * HEADS + h) * 18 + tile) * 8 + wid) * 1024
               + lane * 4;

    #pragma unroll
    for (int nb = 0; nb < 8; nb++) {
        int kj0 = kt * 64 + nb * 8 + 2 * tig;
        int kj1 = kj0 + 1;
        float v[4];
        #pragma unroll
        for (int q = 0; q < 4; q++) {
            int qi = (q < 2) ? qi0 : qi1;
            int kj = (q & 1) ? kj1 : kj0;
            float r;
            if (qi >= N_TOK)      r = 0.f;
            else if (kj >= N_TOK) r = NEGBIG;
            else {
                int p = qi * N_TOK + kj;
                r = (tab[idx[p] * HEADS + h] + mrow[p]) * LOG2E;
            }
            v[q] = r;
        }
        *(float4*)(dst + nb * 128) = make_float4(v[0], v[1], v[2], v[3]);
    }
}

// ================= tensor-core GEMM via mma.sync (tf32) =====================
// out[m][o] = sum_c A[m][c]*W[o][c] (+bias[o]).
// CTA tile 256(M) x 64(N), K=192 in 4 chunks of 48. 8 warps: 4(M) x 2(N),
// warp tile 64x32 = 4x4 m16n8k8 MMAs per k-step, 6 k-steps per chunk.
// Fragment-order SMEM: A fetch = LDS.128, B fetch = LDS.64, conflict-free.
#define GK   192
#define GBK  48
#define NST  6

// As: 16 mb x 6 s x 32 lanes x 4 = 12288 floats
// Bs:  8 nb x 6 s x 32 lanes x 2 =  3072 floats
#define SM_GEMM_FLOATS (12288 + 3072)      // 61440 bytes

template <int DST>
__global__ __launch_bounds__(256, 2)
void gemm_tc(const float* __restrict__ Ain, const float* __restrict__ W,
             const float* __restrict__ bias, float* __restrict__ outp, int ocols) {
    const float* A   = (DST == 0) ? Ain : (const float*)g_att;
    float*       out = (DST == 0) ? (float*)g_qkv : outp;

    extern __shared__ float sm[];
    float* As = sm;            // 12288 floats
    float* Bs = sm + 12288;    // 3072 floats

    const int t    = threadIdx.x;
    const int lane = t & 31;
    const int wid  = t >> 5;
    const int o0   = blockIdx.x * 64;
    const int m0   = blockIdx.y * 256;
    const int wr   = wid >> 1;        // warp M index (0..3) -> 64 rows
    const int wc   = wid & 1;         // warp N index (0..1) -> 32 cols

    float acc[4][4][4];
    #pragma unroll
    for (int im = 0; im < 4; im++)
        #pragma unroll
        for (int jn = 0; jn < 4; jn++)
            #pragma unroll
            for (int q = 0; q < 4; q++) acc[im][jn][q] = 0.f;

    for (int chunk = 0; chunk < 4; chunk++) {
        const int k0 = chunk * GBK;
        __syncthreads();

        // ---- stage A [256 x 48] into fragment order (tf32) ----
        #pragma unroll
        for (int u = 0; u < 12; u++) {
            int e = u * 256 + t;          // 0..3071
            int r = e / 12;               // row 0..255
            int c = (e % 12) * 4;         // col 0..44
            float4 v = *(const float4*)(A + (size_t)(m0 + r) * GK + k0 + c);
            int grp = r & 7, hm = (r >> 3) & 1, mb = r >> 4;
            int s = c >> 3, hk = (c >> 2) & 1;
            int base = (((mb * NST + s) * 32) + grp * 4) * 4 + hm + 2 * hk;
            As[base + 0]  = to_tf32(v.x);
            As[base + 4]  = to_tf32(v.y);
            As[base + 8]  = to_tf32(v.z);
            As[base + 12] = to_tf32(v.w);
        }
        // ---- stage B [64 x 48] into fragment order (tf32) ----
        #pragma unroll
        for (int u = 0; u < 3; u++) {
            int e = u * 256 + t;          // 0..767
            int j = e / 12;               // n row 0..63
            int c = (e % 12) * 4;
            float4 v = *(const float4*)(W + (size_t)(o0 + j) * GK + k0 + c);
            int grp = j & 7, nb = j >> 3;
            int s = c >> 3, hk = (c >> 2) & 1;
            int base = (((nb * NST + s) * 32) + grp * 4) * 2 + hk;
            Bs[base + 0] = to_tf32(v.x);
            Bs[base + 2] = to_tf32(v.y);
            Bs[base + 4] = to_tf32(v.z);
            Bs[base + 6] = to_tf32(v.w);
        }
        __syncthreads();

        // ---- 6 k-steps of 4x4 m16n8k8 ----
        #pragma unroll
        for (int s = 0; s < NST; s++) {
            uint32_t a[4][4];
            #pragma unroll
            for (int im = 0; im < 4; im++) {
                const uint4 av = *(const uint4*)&As[(((wr * 4 + im) * NST + s) * 32 + lane) * 4];
                a[im][0] = av.x; a[im][1] = av.y; a[im][2] = av.z; a[im][3] = av.w;
            }
            uint32_t b[4][2];
            #pragma unroll
            for (int jn = 0; jn < 4; jn++) {
                const uint2 bv = *(const uint2*)&Bs[(((wc * 4 + jn) * NST + s) * 32 + lane) * 2];
                b[jn][0] = bv.x; b[jn][1] = bv.y;
            }
            #pragma unroll
            for (int im = 0; im < 4; im++)
                #pragma unroll
                for (int jn = 0; jn < 4; jn++)
                    mma_tf32(acc[im][jn], a[im], b[jn]);
        }
    }

    const int grp = lane >> 2;
    const int tig = lane & 3;
    #pragma unroll
    for (int im = 0; im < 4; im++) {
        #pragma unroll
        for (int jn = 0; jn < 4; jn++) {
            int col = o0 + wc * 32 + jn * 8 + tig * 2;
            float b0 = 0.f, b1 = 0.f;
            if (bias) { b0 = bias[col]; b1 = bias[col + 1]; }
            int row0 = m0 + wr * 64 + im * 16 + grp;
            float2 v0 = make_float2(acc[im][jn][0] + b0, acc[im][jn][1] + b1);
            float2 v1 = make_float2(acc[im][jn][2] + b0, acc[im][jn][3] + b1);
            *(float2*)(out + (size_t)row0 * ocols + col)       = v0;
            *(float2*)(out + (size_t)(row0 + 8) * ocols + col) = v1;
        }
    }
}

// ================= kernel 3: tensor-core flash attention ====================
// Per CTA: one (b, h, 128-query tile). 8 warps, warp tile 16(M)x64(N keys).
// S = QK^T and O = PV via mma.sync m16n8k8 tf32. Q pre-scaled by SCALE*log2e;
// softmax in exp2 domain; bias+mask read straight into accumulator fragments
// from g_bmt (8 coalesced LDG.128 per thread per tile, no smem round-trip).
//
// SMEM (floats):
//   Qf [8 mb][4 ks][32 lanes][4]  = 4096   A-fragments of Q (persistent)
//   Kf [8 nb][4 ks][32 lanes][2]  = 2048   B-fragments of K (per tile)
//   Vf [8 ks2][4 nb][32 lanes][2] = 2048   B-fragments of V (per tile)
//   Pf [8 warps][8 ks2][128]      = 8192   per-warp P relayout buffer
#define ATT_SM_FLOATS (4096 + 2048 + 2048 + 8192)   // 16384 -> 65536 B

__global__ __launch_bounds__(256, 2) void attn_mma() {
    extern __shared__ float sm[];
    float* Qf = sm;                    // 4096
    float* Kf = sm + 4096;             // 2048
    float* Vf = sm + 6144;             // 2048
    float* Pf = sm + 8192;             // 8192

    const int t    = threadIdx.x;
    const int lane = t & 31;
    const int wid  = t >> 5;
    const int grp  = lane >> 2;
    const int tig  = lane & 3;

    const int qt = blockIdx.x;         // 0..2
    const int q0 = qt * 128;
    const int h  = blockIdx.y;
    const int b  = blockIdx.z;
    const int w  = b & 63;

    const float* qptr = g_qkv + (size_t)b * N_TOK * ODIM + h * HDIM;
    const float* kptr = qptr + CDIM;
    const float* vptr = qptr + 2 * CDIM;
    const float* bmtb = g_bmt + ((((size_t)w * HEADS + h) * 18 + qt * 6) * 8 + wid) * 1024
                      + lane * 4;

    // ---- stage Q [128x32] into A-fragment order (tf32, pre-scaled), once ----
    {
        int r  = t >> 1;                 // 0..127
        int qi = q0 + r;
        int mb = r >> 4, g = r & 7, hm = (r >> 3) & 1;
        int db = (t & 1) * 16;
        #pragma unroll
        for (int c4 = 0; c4 < 4; c4++) {
            int d = db + c4 * 4;
            float4 v = make_float4(0.f, 0.f, 0.f, 0.f);
            if (qi < N_TOK) v = *(const float4*)(qptr + (size_t)qi * ODIM + d);
            int ks = d >> 3, hk = (d >> 2) & 1;
            float* dst = &Qf[mb * 512 + ks * 128 + g * 16 + hm + 2 * hk];
            dst[0]  = to_tf32(v.x * QSCALE);
            dst[4]  = to_tf32(v.y * QSCALE);
            dst[8]  = to_tf32(v.z * QSCALE);
            dst[12] = to_tf32(v.w * QSCALE);
        }
    }

    float mr[2], lr[2];
    mr[0] = NEGBIG; mr[1] = NEGBIG; lr[0] = 0.f; lr[1] = 0.f;
    float o[4][4];
    #pragma unroll
    for (int nb = 0; nb < 4; nb++)
        #pragma unroll
        for (int q = 0; q < 4; q++) o[nb][q] = 0.f;

    for (int kt = 0; kt < 6; kt++) {
        const int k0 = kt * 64;

        // ---- bias+mask fragments straight from gmem (no smem dependency) ----
        float4 bmv[8];
        {
            const float* bt = bmtb + (size_t)kt * 8192;
            #pragma unroll
            for (int nb = 0; nb < 8; nb++)
                bmv[nb] = *(const float4*)(bt + nb * 128);
        }

        __syncthreads();   // prior tile's S/PV done reading Kf/Vf (+Q stage)

        // ---- stage K,V [64x32] into B-fragment order (tf32) ----
        {
            int j  = t >> 2;
            int kj = k0 + j;
            bool vld = kj < N_TOK;
            int db = (t & 3) * 8;
            float4 k0v = make_float4(0.f, 0.f, 0.f, 0.f), k1v = k0v;
            float4 v0v = k0v, v1v = k0v;
            if (vld) {
                k0v = *(const float4*)(kptr + (size_t)kj * ODIM + db);
                k1v = *(const float4*)(kptr + (size_t)kj * ODIM + db + 4);
                v0v = *(const float4*)(vptr + (size_t)kj * ODIM + db);
                v1v = *(const float4*)(vptr + (size_t)kj * ODIM + db + 4);
            }
            {   // K: (key j, d) -> Kf[(j>>3)*256 + (d>>3)*64 + (j&7)*8 + (d&3)*2 + ((d>>2)&1)]
                float* kd = &Kf[(j >> 3) * 256 + (db >> 3) * 64 + (j & 7) * 8];
                float4 w0 = make_float4(to_tf32(k0v.x), to_tf32(k1v.x),
                                        to_tf32(k0v.y), to_tf32(k1v.y));
                float4 w1 = make_float4(to_tf32(k0v.z), to_tf32(k1v.z),
                                        to_tf32(k0v.w), to_tf32(k1v.w));
                *(float4*)(kd + 0) = w0;
                *(float4*)(kd + 4) = w1;
            }
            {   // V: (k=j, n=d) -> Vf[(j>>3)*256 + (d>>3)*64 + (d&7)*8 + ((j&7)&3)*2 + ((j&7)>>2)]
                float* vd = &Vf[(j >> 3) * 256 + (db >> 3) * 64 + ((j & 7) & 3) * 2 + ((j & 7) >> 2)];
                vd[0]  = to_tf32(v0v.x);
                vd[8]  = to_tf32(v0v.y);
                vd[16] = to_tf32(v0v.z);
                vd[24] = to_tf32(v0v.w);
                vd[32] = to_tf32(v1v.x);
                vd[40] = to_tf32(v1v.y);
                vd[48] = to_tf32(v1v.z);
                vd[56] = to_tf32(v1v.w);
            }
        }
        __syncthreads();

        // ---- S = Q K^T : warp tile 16x64 ----
        float s[8][4];
        #pragma unroll
        for (int nb = 0; nb < 8; nb++)
            #pragma unroll
            for (int q = 0; q < 4; q++) s[nb][q] = 0.f;

        #pragma unroll
        for (int ks = 0; ks < 4; ks++) {
            uint32_t a[4];
            const uint4 av = *(const uint4*)&Qf[wid * 512 + ks * 128 + lane * 4];
            a[0] = av.x; a[1] = av.y; a[2] = av.z; a[3] = av.w;
            #pragma unroll
            for (int nb = 0; nb < 8; nb++) {
                uint32_t bfr[2];
                const uint2 bv = *(const uint2*)&Kf[nb * 256 + ks * 64 + lane * 2];
                bfr[0] = bv.x; bfr[1] = bv.y;
                mma_tf32(s[nb], a, bfr);
            }
        }

        // ---- online softmax in exp2 domain (rows grp, grp+8) ----
        float rmax0 = NEGBIG, rmax1 = NEGBIG;
        #pragma unroll
        for (int nb = 0; nb < 8; nb++) {
            s[nb][0] += bmv[nb].x;
            s[nb][1] += bmv[nb].y;
            s[nb][2] += bmv[nb].z;
            s[nb][3] += bmv[nb].w;
            rmax0 = fmaxf(rmax0, fmaxf(s[nb][0], s[nb][1]));
            rmax1 = fmaxf(rmax1, fmaxf(s[nb][2], s[nb][3]));
        }
        rmax0 = fmaxf(rmax0, __shfl_xor_sync(0xffffffffu, rmax0, 1));
        rmax0 = fmaxf(rmax0, __shfl_xor_sync(0xffffffffu, rmax0, 2));
        rmax1 = fmaxf(rmax1, __shfl_xor_sync(0xffffffffu, rmax1, 1));
        rmax1 = fmaxf(rmax1, __shfl_xor_sync(0xffffffffu, rmax1, 2));

        float mn0 = fmaxf(mr[0], rmax0);
        float mn1 = fmaxf(mr[1], rmax1);
        float al0 = exp2f(mr[0] - mn0);
        float al1 = exp2f(mr[1] - mn1);
        mr[0] = mn0; mr[1] = mn1;

        float rs0 = 0.f, rs1 = 0.f;
        float* pw = Pf + wid * 1024 + grp * 16;
        const int off0 = ((2 * tig) & 3) * 4 + ((2 * tig) >> 2) * 2;
        const int off1 = ((2 * tig + 1) & 3) * 4 + ((2 * tig + 1) >> 2) * 2;
        #pragma unroll
        for (int nb = 0; nb < 8; nb++) {
            float p00 = exp2f(s[nb][0] - mn0);
            float p01 = exp2f(s[nb][1] - mn0);
            float p10 = exp2f(s[nb][2] - mn1);
            float p11 = exp2f(s[nb][3] - mn1);
            rs0 += p00 + p01;
            rs1 += p10 + p11;
            // S col-block nb == PV k-block; write P in PV A-fragment layout
            *(float2*)&pw[nb * 128 + off0] = make_float2(to_tf32(p00), to_tf32(p10));
            *(float2*)&pw[nb * 128 + off1] = make_float2(to_tf32(p01), to_tf32(p11));
        }
        rs0 += __shfl_xor_sync(0xffffffffu, rs0, 1);
        rs0 += __shfl_xor_sync(0xffffffffu, rs0, 2);
        rs1 += __shfl_xor_sync(0xffffffffu, rs1, 1);
        rs1 += __shfl_xor_sync(0xffffffffu, rs1, 2);
        lr[0] = lr[0] * al0 + rs0;
        lr[1] = lr[1] * al1 + rs1;

        // rescale O
        #pragma unroll
        for (int nb = 0; nb < 4; nb++) {
            o[nb][0] *= al0; o[nb][1] *= al0;
            o[nb][2] *= al1; o[nb][3] *= al1;
        }
        __syncwarp();   // Pf is per-warp: order STS before cross-lane LDS

        // ---- O += P V : 64 keys = 8 k-steps ----
        #pragma unroll
        for (int ks2 = 0; ks2 < 8; ks2++) {
            uint32_t a[4];
            const uint4 av = *(const uint4*)&Pf[wid * 1024 + ks2 * 128 + lane * 4];
            a[0] = av.x; a[1] = av.y; a[2] = av.z; a[3] = av.w;
            #pragma unroll
            for (int nb = 0; nb < 4; nb++) {
                uint32_t bfr[2];
                const uint2 bv = *(const uint2*)&Vf[ks2 * 256 + nb * 64 + lane * 2];
                bfr[0] = bv.x; bfr[1] = bv.y;
                mma_tf32(o[nb], a, bfr);
            }
        }
    }

    // ---- normalize + store [b, n, h*32+d] ----
    {
        float inv0 = 1.f / lr[0];
        float inv1 = 1.f / lr[1];
        int row0 = q0 + wid * 16 + grp;
        int row1 = row0 + 8;
        #pragma unroll
        for (int nb = 0; nb < 4; nb++) {
            int col = h * HDIM + nb * 8 + 2 * tig;
            if (row0 < N_TOK)
                *(float2*)&g_att[((size_t)b * N_TOK + row0) * CDIM + col] =
                    make_float2(o[nb][0] * inv0, o[nb][1] * inv0);
            if (row1 < N_TOK)
                *(float2*)&g_att[((size_t)b * N_TOK + row1) * CDIM + col] =
                    make_float2(o[nb][2] * inv1, o[nb][3] * inv1);
        }
    }
}

// ---------------- launch ----------------------------------------------------
extern "C" void kernel_launch(void* const* d_in, const int* in_sizes, int n_in,
                              void* d_out, int out_size) {
    (void)in_sizes; (void)n_in; (void)out_size;
    const float* x        = (const float*)d_in[0];
    const float* mask     = (const float*)d_in[1];
    const float* qkv_w    = (const float*)d_in[2];
    const float* proj_w   = (const float*)d_in[3];
    const float* proj_b   = (const float*)d_in[4];
    const float* bias_tab = (const float*)d_in[5];
    const int*   rel_idx  = (const int*)d_in[6];
    float* out = (float*)d_out;

    cudaFuncSetAttribute(attn_mma,
                         cudaFuncAttributeMaxDynamicSharedMemorySize,
                         ATT_SM_FLOATS * 4);
    cudaFuncSetAttribute(gemm_tc<0>,
                         cudaFuncAttributeMaxDynamicSharedMemorySize,
                         SM_GEMM_FLOATS * 4);
    cudaFuncSetAttribute(gemm_tc<1>,
                         cudaFuncAttributeMaxDynamicSharedMemorySize,
                         SM_GEMM_FLOATS * 4);

    bm_precompute<<<dim3(18, HEADS, 64), 256>>>(bias_tab, rel_idx, mask);
    gemm_tc<0><<<dim3(ODIM / 64, MROWS / 256), 256, SM_GEMM_FLOATS * 4>>>(
        x, qkv_w, nullptr, nullptr, ODIM);
    attn_mma<<<dim3(3, HEADS, BATCH), 256, ATT_SM_FLOATS * 4>>>();
    gemm_tc<1><<<dim3(CDIM / 64, MROWS / 256), 256, SM_GEMM_FLOATS * 4>>>(
        nullptr, proj_w, proj_b, out, CDIM);
}

// round 12
// speedup vs baseline: 2.1137x; 1.0433x over previous
#include <cuda_runtime.h>
#include <cstdint>

#define N_TOK 343
#define BATCH 256
#define HEADS 6
#define HDIM  32
#define CDIM  192
#define ODIM  576            // 3*C
#define MROWS 87808          // BATCH*N_TOK
#define NN2   117649         // 343*343
#define SCALE 0.17677669529663687f
#define LOG2E 1.4426950408889634f
#define QSCALE (SCALE * LOG2E)
#define NEGBIG (-1e30f)

// ---------------- scratch (device globals: no runtime allocation allowed) ----
// NOTE: only reference these from device code (host shadow trap — R5 bug).
__device__ float g_qkv[(size_t)MROWS * ODIM];      // [B*N, 3C]
__device__ float g_att[(size_t)MROWS * CDIM];      // [B*N, C]
// bias+mask in MMA-fragment tile order:
// [w][h][qt(3)*6+kt][wid(8)][nb(8)][lane(32)][4]  (8192 floats per 128x64 tile)
__device__ float g_bmt[(size_t)64 * HEADS * 18 * 8192];

// ---------------- common helpers -------------------------------------------
__device__ __forceinline__ float to_tf32(float x) {
    uint32_t u;
    asm("cvt.rna.tf32.f32 %0, %1;" : "=r"(u) : "f"(x));
    return __uint_as_float(u);
}

__device__ __forceinline__ void mma_tf32(float* d, const uint32_t* a, const uint32_t* b) {
    asm volatile(
        "mma.sync.aligned.m16n8k8.row.col.f32.tf32.tf32.f32 "
        "{%0,%1,%2,%3}, {%4,%5,%6,%7}, {%8,%9}, {%0,%1,%2,%3};\n"
        : "+f"(d[0]), "+f"(d[1]), "+f"(d[2]), "+f"(d[3])
        : "r"(a[0]), "r"(a[1]), "r"(a[2]), "r"(a[3]), "r"(b[0]), "r"(b[1]));
}

// ---------------- kernel 1: bias+mask -> fragment-tiled layout -------------
__global__ __launch_bounds__(256) void bm_precompute(
        const float* __restrict__ tab,
        const int* __restrict__ idx,
        const float* __restrict__ mask) {
    const int tile = blockIdx.x;        // qt*6 + kt
    const int h    = blockIdx.y;
    const int w    = blockIdx.z;
    const int qt   = tile / 6;
    const int kt   = tile % 6;
    const int t    = threadIdx.x;
    const int lane = t & 31;
    const int wid  = t >> 5;
    const int grp  = lane >> 2;
    const int tig  = lane & 3;

    const int qi0 = qt * 128 + wid * 16 + grp;
    const int qi1 = qi0 + 8;
    const float* mrow = mask + (size_t)w * NN2;

    float* dst = g_bmt + ((((size_t)w * HEADS + h) * 18 + tile) * 8 + wid) * 1024
               + lane * 4;

    #pragma unroll
    for (int nb = 0; nb < 8; nb++) {
        int kj0 = kt * 64 + nb * 8 + 2 * tig;
        int kj1 = kj0 + 1;
        float v[4];
        #pragma unroll
        for (int q = 0; q < 4; q++) {
            int qi = (q < 2) ? qi0 : qi1;
            int kj = (q & 1) ? kj1 : kj0;
            float r;
            if (qi >= N_TOK)      r = 0.f;
            else if (kj >= N_TOK) r = NEGBIG;
            else {
                int p = qi * N_TOK + kj;
                r = (tab[idx[p] * HEADS + h] + mrow[p]) * LOG2E;
            }
            v[q] = r;
        }
        *(float4*)(dst + nb * 128) = make_float4(v[0], v[1], v[2], v[3]);
    }
}

// ================= tensor-core GEMM via mma.sync (tf32) =====================
// CTA tile 256(M) x 64(N), K=192 in 8 software-pipelined chunks of 24.
// 8 warps 4(M)x2(N), warp tile 64x32 = 4x4 m16n8k8, 3 k-steps per chunk.
// Pipeline: sync -> cvt+STS(chunk c from regs) -> LDG(chunk c+1 into SAME
// regs; WAR scoreboarded) -> sync -> compute(c). LDG latency hides under MMA.
#define GK     192
#define GBK    24
#define NST    3
#define NCHK   8

// As: 16 mb x 3 s x 32 lanes x 4 = 6144 ; Bs: 8 nb x 3 s x 32 lanes x 2 = 1536
#define SM_GEMM_FLOATS (6144 + 1536)       // 30720 bytes

template <int DST>
__global__ __launch_bounds__(256, 2)
void gemm_tc(const float* __restrict__ Ain, const float* __restrict__ W,
             const float* __restrict__ bias, float* __restrict__ outp, int ocols) {
    const float* A   = (DST == 0) ? Ain : (const float*)g_att;
    float*       out = (DST == 0) ? (float*)g_qkv : outp;

    extern __shared__ float sm[];
    float* As = sm;            // 6144 floats
    float* Bs = sm + 6144;     // 1536 floats

    const int t    = threadIdx.x;
    const int lane = t & 31;
    const int wid  = t >> 5;
    const int o0   = blockIdx.x * 64;
    const int m0   = blockIdx.y * 256;
    const int wr   = wid >> 1;        // warp M index (0..3) -> 64 rows
    const int wc   = wid & 1;         // warp N index (0..1) -> 32 cols

    float acc[4][4][4];
    #pragma unroll
    for (int im = 0; im < 4; im++)
        #pragma unroll
        for (int jn = 0; jn < 4; jn++)
            #pragma unroll
            for (int q = 0; q < 4; q++) acc[im][jn][q] = 0.f;

    float4 pa[6];
    float2 pb[3];

    // ---- prologue: prefetch chunk 0 ----
    #pragma unroll
    for (int u = 0; u < 6; u++) {
        int e = u * 256 + t;
        int r = e / 6;
        int c = (e % 6) * 4;
        pa[u] = *(const float4*)(A + (size_t)(m0 + r) * GK + c);
    }
    #pragma unroll
    for (int u = 0; u < 3; u++) {
        int e = u * 256 + t;
        int j = e / 12;
        int c = (e % 12) * 2;
        pb[u] = *(const float2*)(W + (size_t)(o0 + j) * GK + c);
    }

    for (int chunk = 0; chunk < NCHK; chunk++) {
        __syncthreads();   // prior compute done reading fragment smem

        // ---- cvt + STS chunk from prefetch regs ----
        #pragma unroll
        for (int u = 0; u < 6; u++) {
            int e = u * 256 + t;
            int r = e / 6;
            int c = (e % 6) * 4;
            int grp = r & 7, hm = (r >> 3) & 1, mb = r >> 4;
            int s = c >> 3, hk = (c >> 2) & 1;
            int base = (((mb * NST + s) * 32) + grp * 4) * 4 + hm + 2 * hk;
            As[base + 0]  = to_tf32(pa[u].x);
            As[base + 4]  = to_tf32(pa[u].y);
            As[base + 8]  = to_tf32(pa[u].z);
            As[base + 12] = to_tf32(pa[u].w);
        }
        #pragma unroll
        for (int u = 0; u < 3; u++) {
            int e = u * 256 + t;
            int j = e / 12;
            int c = (e % 12) * 2;          // even k: pair shares s,hk
            int grp = j & 7, nb = j >> 3;
            int s = c >> 3, hk = (c >> 2) & 1, q = c & 3;
            int idx0 = ((nb * NST + s) * 32 + grp * 4 + q) * 2 + hk;
            Bs[idx0]     = to_tf32(pb[u].x);
            Bs[idx0 + 2] = to_tf32(pb[u].y);
        }

        // ---- prefetch next chunk into the SAME regs (WAR after STS) ----
        if (chunk < NCHK - 1) {
            const int k0n = (chunk + 1) * GBK;
            #pragma unroll
            for (int u = 0; u < 6; u++) {
                int e = u * 256 + t;
                int r = e / 6;
                int c = (e % 6) * 4;
                pa[u] = *(const float4*)(A + (size_t)(m0 + r) * GK + k0n + c);
            }
            #pragma unroll
            for (int u = 0; u < 3; u++) {
                int e = u * 256 + t;
                int j = e / 12;
                int c = (e % 12) * 2;
                pb[u] = *(const float2*)(W + (size_t)(o0 + j) * GK + k0n + c);
            }
        }
        __syncthreads();

        // ---- compute: 3 k-steps of 4x4 m16n8k8 (LDG latency hides here) ----
        #pragma unroll
        for (int s = 0; s < NST; s++) {
            uint32_t a[4][4];
            #pragma unroll
            for (int im = 0; im < 4; im++) {
                const uint4 av = *(const uint4*)&As[(((wr * 4 + im) * NST + s) * 32 + lane) * 4];
                a[im][0] = av.x; a[im][1] = av.y; a[im][2] = av.z; a[im][3] = av.w;
            }
            uint32_t b[4][2];
            #pragma unroll
            for (int jn = 0; jn < 4; jn++) {
                const uint2 bv = *(const uint2*)&Bs[(((wc * 4 + jn) * NST + s) * 32 + lane) * 2];
                b[jn][0] = bv.x; b[jn][1] = bv.y;
            }
            #pragma unroll
            for (int im = 0; im < 4; im++)
                #pragma unroll
                for (int jn = 0; jn < 4; jn++)
                    mma_tf32(acc[im][jn], a[im], b[jn]);
        }
    }

    const int grp = lane >> 2;
    const int tig = lane & 3;
    #pragma unroll
    for (int im = 0; im < 4; im++) {
        #pragma unroll
        for (int jn = 0; jn < 4; jn++) {
            int col = o0 + wc * 32 + jn * 8 + tig * 2;
            float b0 = 0.f, b1 = 0.f;
            if (bias) { b0 = bias[col]; b1 = bias[col + 1]; }
            int row0 = m0 + wr * 64 + im * 16 + grp;
            float2 v0 = make_float2(acc[im][jn][0] + b0, acc[im][jn][1] + b1);
            float2 v1 = make_float2(acc[im][jn][2] + b0, acc[im][jn][3] + b1);
            *(float2*)(out + (size_t)row0 * ocols + col)       = v0;
            *(float2*)(out + (size_t)(row0 + 8) * ocols + col) = v1;
        }
    }
}

// ================= kernel 3: tensor-core flash attention ====================
// As R11, plus software-pipelined K/V staging: LDG for tile kt+1 issues right
// after tile kt's STS (same regs, WAR) and hides under S/softmax/PV compute.
#define ATT_SM_FLOATS (4096 + 2048 + 2048 + 8192)   // 16384 -> 65536 B

__global__ __launch_bounds__(256, 2) void attn_mma() {
    extern __shared__ float sm[];
    float* Qf = sm;                    // 4096
    float* Kf = sm + 4096;             // 2048
    float* Vf = sm + 6144;             // 2048
    float* Pf = sm + 8192;             // 8192

    const int t    = threadIdx.x;
    const int lane = t & 31;
    const int wid  = t >> 5;
    const int grp  = lane >> 2;
    const int tig  = lane & 3;

    const int qt = blockIdx.x;         // 0..2
    const int q0 = qt * 128;
    const int h  = blockIdx.y;
    const int b  = blockIdx.z;
    const int w  = b & 63;

    const float* qptr = g_qkv + (size_t)b * N_TOK * ODIM + h * HDIM;
    const float* kptr = qptr + CDIM;
    const float* vptr = qptr + 2 * CDIM;
    const float* bmtb = g_bmt + ((((size_t)w * HEADS + h) * 18 + qt * 6) * 8 + wid) * 1024
                      + lane * 4;

    // per-thread K/V staging geometry
    const int jj = t >> 2;             // key row 0..63
    const int db = (t & 3) * 8;        // d base

    // ---- prologue: prefetch K/V tile 0 ----
    float4 kva, kvb, kvc, kvd;
    {
        bool vld = jj < N_TOK;
        kva = kvb = kvc = kvd = make_float4(0.f, 0.f, 0.f, 0.f);
        if (vld) {
            kva = *(const float4*)(kptr + (size_t)jj * ODIM + db);
            kvb = *(const float4*)(kptr + (size_t)jj * ODIM + db + 4);
            kvc = *(const float4*)(vptr + (size_t)jj * ODIM + db);
            kvd = *(const float4*)(vptr + (size_t)jj * ODIM + db + 4);
        }
    }

    // ---- stage Q [128x32] into A-fragment order (tf32, pre-scaled), once ----
    {
        int r  = t >> 1;                 // 0..127
        int qi = q0 + r;
        int mb = r >> 4, g = r & 7, hm = (r >> 3) & 1;
        int dbq = (t & 1) * 16;
        #pragma unroll
        for (int c4 = 0; c4 < 4; c4++) {
            int d = dbq + c4 * 4;
            float4 v = make_float4(0.f, 0.f, 0.f, 0.f);
            if (qi < N_TOK) v = *(const float4*)(qptr + (size_t)qi * ODIM + d);
            int ks = d >> 3, hk = (d >> 2) & 1;
            float* dst = &Qf[mb * 512 + ks * 128 + g * 16 + hm + 2 * hk];
            dst[0]  = to_tf32(v.x * QSCALE);
            dst[4]  = to_tf32(v.y * QSCALE);
            dst[8]  = to_tf32(v.z * QSCALE);
            dst[12] = to_tf32(v.w * QSCALE);
        }
    }

    float mr[2], lr[2];
    mr[0] = NEGBIG; mr[1] = NEGBIG; lr[0] = 0.f; lr[1] = 0.f;
    float o[4][4];
    #pragma unroll
    for (int nb = 0; nb < 4; nb++)
        #pragma unroll
        for (int q = 0; q < 4; q++) o[nb][q] = 0.f;

    for (int kt = 0; kt < 6; kt++) {
        // ---- bias+mask fragments straight from gmem (consumed in softmax) ----
        float4 bmv[8];
        {
            const float* bt = bmtb + (size_t)kt * 8192;
            #pragma unroll
            for (int nb = 0; nb < 8; nb++)
                bmv[nb] = *(const float4*)(bt + nb * 128);
        }

        __syncthreads();   // prior tile's S/PV done reading Kf/Vf (+Q stage)

        // ---- STS K/V from prefetch regs ----
        {
            float* kd = &Kf[(jj >> 3) * 256 + (db >> 3) * 64 + (jj & 7) * 8];
            float4 w0 = make_float4(to_tf32(kva.x), to_tf32(kvb.x),
                                    to_tf32(kva.y), to_tf32(kvb.y));
            float4 w1 = make_float4(to_tf32(kva.z), to_tf32(kvb.z),
                                    to_tf32(kva.w), to_tf32(kvb.w));
            *(float4*)(kd + 0) = w0;
            *(float4*)(kd + 4) = w1;

            float* vd = &Vf[(jj >> 3) * 256 + (db >> 3) * 64 + ((jj & 7) & 3) * 2 + ((jj & 7) >> 2)];
            vd[0]  = to_tf32(kvc.x);
            vd[8]  = to_tf32(kvc.y);
            vd[16] = to_tf32(kvc.z);
            vd[24] = to_tf32(kvc.w);
            vd[32] = to_tf32(kvd.x);
            vd[40] = to_tf32(kvd.y);
            vd[48] = to_tf32(kvd.z);
            vd[56] = to_tf32(kvd.w);
        }

        // ---- prefetch K/V tile kt+1 into SAME regs (hides under compute) ----
        if (kt < 5) {
            int kj = (kt + 1) * 64 + jj;
            bool vld = kj < N_TOK;
            kva = kvb = kvc = kvd = make_float4(0.f, 0.f, 0.f, 0.f);
            if (vld) {
                kva = *(const float4*)(kptr + (size_t)kj * ODIM + db);
                kvb = *(const float4*)(kptr + (size_t)kj * ODIM + db + 4);
                kvc = *(const float4*)(vptr + (size_t)kj * ODIM + db);
                kvd = *(const float4*)(vptr + (size_t)kj * ODIM + db + 4);
            }
        }
        __syncthreads();

        // ---- S = Q K^T : warp tile 16x64 ----
        float s[8][4];
        #pragma unroll
        for (int nb = 0; nb < 8; nb++)
            #pragma unroll
            for (int q = 0; q < 4; q++) s[nb][q] = 0.f;

        #pragma unroll
        for (int ks = 0; ks < 4; ks++) {
            uint32_t a[4];
            const uint4 av = *(const uint4*)&Qf[wid * 512 + ks * 128 + lane * 4];
            a[0] = av.x; a[1] = av.y; a[2] = av.z; a[3] = av.w;
            #pragma unroll
            for (int nb = 0; nb < 8; nb++) {
                uint32_t bfr[2];
                const uint2 bv = *(const uint2*)&Kf[nb * 256 + ks * 64 + lane * 2];
                bfr[0] = bv.x; bfr[1] = bv.y;
                mma_tf32(s[nb], a, bfr);
            }
        }

        // ---- online softmax in exp2 domain (rows grp, grp+8) ----
        float rmax0 = NEGBIG, rmax1 = NEGBIG;
        #pragma unroll
        for (int nb = 0; nb < 8; nb++) {
            s[nb][0] += bmv[nb].x;
            s[nb][1] += bmv[nb].y;
            s[nb][2] += bmv[nb].z;
            s[nb][3] += bmv[nb].w;
            rmax0 = fmaxf(rmax0, fmaxf(s[nb][0], s[nb][1]));
            rmax1 = fmaxf(rmax1, fmaxf(s[nb][2], s[nb][3]));
        }
        rmax0 = fmaxf(rmax0, __shfl_xor_sync(0xffffffffu, rmax0, 1));
        rmax0 = fmaxf(rmax0, __shfl_xor_sync(0xffffffffu, rmax0, 2));
        rmax1 = fmaxf(rmax1, __shfl_xor_sync(0xffffffffu, rmax1, 1));
        rmax1 = fmaxf(rmax1, __shfl_xor_sync(0xffffffffu, rmax1, 2));

        float mn0 = fmaxf(mr[0], rmax0);
        float mn1 = fmaxf(mr[1], rmax1);
        float al0 = exp2f(mr[0] - mn0);
        float al1 = exp2f(mr[1] - mn1);
        mr[0] = mn0; mr[1] = mn1;

        float rs0 = 0.f, rs1 = 0.f;
        float* pw = Pf + wid * 1024 + grp * 16;
        const int off0 = ((2 * tig) & 3) * 4 + ((2 * tig) >> 2) * 2;
        const int off1 = ((2 * tig + 1) & 3) * 4 + ((2 * tig + 1) >> 2) * 2;
        #pragma unroll
        for (int nb = 0; nb < 8; nb++) {
            float p00 = exp2f(s[nb][0] - mn0);
            float p01 = exp2f(s[nb][1] - mn0);
            float p10 = exp2f(s[nb][2] - mn1);
            float p11 = exp2f(s[nb][3] - mn1);
            rs0 += p00 + p01;
            rs1 += p10 + p11;
            // S col-block nb == PV k-block; write P in PV A-fragment layout
            *(float2*)&pw[nb * 128 + off0] = make_float2(to_tf32(p00), to_tf32(p10));
            *(float2*)&pw[nb * 128 + off1] = make_float2(to_tf32(p01), to_tf32(p11));
        }
        rs0 += __shfl_xor_sync(0xffffffffu, rs0, 1);
        rs0 += __shfl_xor_sync(0xffffffffu, rs0, 2);
        rs1 += __shfl_xor_sync(0xffffffffu, rs1, 1);
        rs1 += __shfl_xor_sync(0xffffffffu, rs1, 2);
        lr[0] = lr[0] * al0 + rs0;
        lr[1] = lr[1] * al1 + rs1;

        // rescale O
        #pragma unroll
        for (int nb = 0; nb < 4; nb++) {
            o[nb][0] *= al0; o[nb][1] *= al0;
            o[nb][2] *= al1; o[nb][3] *= al1;
        }
        __syncwarp();   // Pf is per-warp: order STS before cross-lane LDS

        // ---- O += P V : 64 keys = 8 k-steps ----
        #pragma unroll
        for (int ks2 = 0; ks2 < 8; ks2++) {
            uint32_t a[4];
            const uint4 av = *(const uint4*)&Pf[wid * 1024 + ks2 * 128 + lane * 4];
            a[0] = av.x; a[1] = av.y; a[2] = av.z; a[3] = av.w;
            #pragma unroll
            for (int nb = 0; nb < 4; nb++) {
                uint32_t bfr[2];
                const uint2 bv = *(const uint2*)&Vf[ks2 * 256 + nb * 64 + lane * 2];
                bfr[0] = bv.x; bfr[1] = bv.y;
                mma_tf32(o[nb], a, bfr);
            }
        }
    }

    // ---- normalize + store [b, n, h*32+d] ----
    {
        float inv0 = 1.f / lr[0];
        float inv1 = 1.f / lr[1];
        int row0 = q0 + wid * 16 + grp;
        int row1 = row0 + 8;
        #pragma unroll
        for (int nb = 0; nb < 4; nb++) {
            int col = h * HDIM + nb * 8 + 2 * tig;
            if (row0 < N_TOK)
                *(float2*)&g_att[((size_t)b * N_TOK + row0) * CDIM + col] =
                    make_float2(o[nb][0] * inv0, o[nb][1] * inv0);
            if (row1 < N_TOK)
                *(float2*)&g_att[((size_t)b * N_TOK + row1) * CDIM + col] =
                    make_float2(o[nb][2] * inv1, o[nb][3] * inv1);
        }
    }
}

// ---------------- launch ----------------------------------------------------
extern "C" void kernel_launch(void* const* d_in, const int* in_sizes, int n_in,
                              void* d_out, int out_size) {
    (void)in_sizes; (void)n_in; (void)out_size;
    const float* x        = (const float*)d_in[0];
    const float* mask     = (const float*)d_in[1];
    const float* qkv_w    = (const float*)d_in[2];
    const float* proj_w   = (const float*)d_in[3];
    const float* proj_b   = (const float*)d_in[4];
    const float* bias_tab = (const float*)d_in[5];
    const int*   rel_idx  = (const int*)d_in[6];
    float* out = (float*)d_out;

    cudaFuncSetAttribute(attn_mma,
                         cudaFuncAttributeMaxDynamicSharedMemorySize,
                         ATT_SM_FLOATS * 4);
    cudaFuncSetAttribute(gemm_tc<0>,
                         cudaFuncAttributeMaxDynamicSharedMemorySize,
                         SM_GEMM_FLOATS * 4);
    cudaFuncSetAttribute(gemm_tc<1>,
                         cudaFuncAttributeMaxDynamicSharedMemorySize,
                         SM_GEMM_FLOATS * 4);

    bm_precompute<<<dim3(18, HEADS, 64), 256>>>(bias_tab, rel_idx, mask);
    gemm_tc<0><<<dim3(ODIM / 64, MROWS / 256), 256, SM_GEMM_FLOATS * 4>>>(
        x, qkv_w, nullptr, nullptr, ODIM);
    attn_mma<<<dim3(3, HEADS, BATCH), 256, ATT_SM_FLOATS * 4>>>();
    gemm_tc<1><<<dim3(CDIM / 64, MROWS / 256), 256, SM_GEMM_FLOATS * 4>>>(
        nullptr, proj_w, proj_b, out, CDIM);
}